// round 14
// baseline (speedup 1.0000x reference)
#include <cuda_runtime.h>
#include <cuda_bf16.h>
#include <math.h>
#include <stdint.h>

// Problem constants
#define BB   4
#define SS   2048
#define HD   1024
#define NHH  16
#define DD   64
#define FFD  4096
#define BSR  (BB*SS)          // 8192 rows
#define LOG2E 1.4426950408889634f

// ---------------- scratch (device globals: no allocation allowed) ----------
__device__ float g_q  [BSR * HD];
__device__ float g_k  [BSR * HD];
__device__ float g_v  [BSR * HD];
__device__ float g_ctx[BSR * HD];
__device__ float g_r1 [BSR * HD];
__device__ float g_h  [BSR * HD];
__device__ float g_ff [BSR * FFD];
__device__ float g_r2 [BSR * HD];
// packed transposed (N,K) tf32-rounded weights
__device__ float g_wqkvt[3 * HD * HD];
__device__ float g_bqkv [3 * HD];
__device__ float g_wot[HD * HD];
__device__ float g_w1t[FFD * HD];
__device__ float g_w2t[HD * FFD];
// rope cos/sin table [S][32]
__device__ float2 g_ropetab[SS * 32];

__device__ __forceinline__ float tf32r(float x) {
    float r;
    asm("cvt.rna.tf32.f32 %0, %1;" : "=f"(r) : "f"(x));
    return r;
}
__device__ __forceinline__ float tanh_fast(float x) {
    float y;
    asm("tanh.approx.f32 %0, %1;" : "=f"(y) : "f"(x));
    return y;
}
__device__ __forceinline__ uint32_t smem_u32(const void* p) {
    uint32_t a;
    asm("{ .reg .u64 t; cvta.to.shared.u64 t, %1; cvt.u32.u64 %0, t; }" : "=r"(a) : "l"(p));
    return a;
}
__device__ __forceinline__ void cp_async16(uint32_t saddr, const void* g) {
    asm volatile("cp.async.cg.shared.global [%0], [%1], 16;" :: "r"(saddr), "l"(g));
}
__device__ __forceinline__ void cp_commit() {
    asm volatile("cp.async.commit_group;" ::: "memory");
}
template<int N> __device__ __forceinline__ void cp_wait() {
    asm volatile("cp.async.wait_group %0;" :: "n"(N) : "memory");
}

// fast exp2 on the fma/alu pipes (valid for x <= ~0; clamps at -126)
__device__ __forceinline__ float fexp2(float x) {
    x = fmaxf(x, -126.f);
    const float k = x + 12582912.f;
    const int   ik = __float_as_int(k) - 0x4B400000;
    const float f = x - (k - 12582912.f);
    float p = 9.6181291e-3f;
    p = fmaf(p, f, 5.5504109e-2f);
    p = fmaf(p, f, 2.4022651e-1f);
    p = fmaf(p, f, 6.9314718e-1f);
    p = fmaf(p, f, 1.0f);
    return __int_as_float(__float_as_int(p) + (ik << 23));
}

__device__ __forceinline__ void mma_tf32_16x8x8(float* c, const uint32_t* a, const uint32_t* b) {
    asm volatile(
        "mma.sync.aligned.m16n8k8.row.col.f32.tf32.tf32.f32 "
        "{%0,%1,%2,%3}, {%4,%5,%6,%7}, {%8,%9}, {%0,%1,%2,%3};"
        : "+f"(c[0]), "+f"(c[1]), "+f"(c[2]), "+f"(c[3])
        : "r"(a[0]), "r"(a[1]), "r"(a[2]), "r"(a[3]), "r"(b[0]), "r"(b[1]));
}

// =================== tf32 mma.sync GEMM (3-stage cp.async) =================
// EPI: 0 = bias(+add), 1 = bias+gelu, 2 = fused QKV + RoPE
// BM=BN=128, BK=32, 128 threads (4 warps), warp tile 64x64.
#define AST 36
#define GBUF (128 * AST)

__device__ __forceinline__ void stage_copy(const float* __restrict__ A,
                                           const float* __restrict__ Bt,
                                           int K, int crow, int ccol, int k0,
                                           float* sa, float* sb, int tid)
{
    const int r0 = tid >> 3;          // 0..15
    const int c  = (tid & 7) * 4;     // 0..28
    #pragma unroll
    for (int i = 0; i < 8; i++) {
        const int row = i * 16 + r0;
        cp_async16(smem_u32(sa + row * AST + c), A  + (size_t)(crow + row) * K + k0 + c);
        cp_async16(smem_u32(sb + row * AST + c), Bt + (size_t)(ccol + row) * K + k0 + c);
    }
}

template<int EPI>
__global__ __launch_bounds__(128, 2)
void gemm_mma(const float* __restrict__ A, const float* __restrict__ Bt,
              const float* __restrict__ bias, const float* __restrict__ add,
              float* __restrict__ C, int M, int N, int K,
              float* __restrict__ Ck = nullptr, float* __restrict__ Cv = nullptr)
{
    extern __shared__ float smem[];
    float* As = smem;
    float* Bs = smem + 3 * GBUF;

    const int tid  = threadIdx.x;
    const int wid  = tid >> 5;        // 0..3
    const int lane = tid & 31;
    const int g    = lane >> 2;
    const int t    = lane & 3;

    const int crow = blockIdx.y * 128;
    const int ccol = blockIdx.x * 128;

    const int rb = (wid & 1) * 64;    // 2x2 warp grid, 64x64 tiles
    const int cb = (wid >> 1) * 64;

    float acc[4][8][4];
    #pragma unroll
    for (int i = 0; i < 4; i++)
        #pragma unroll
        for (int j = 0; j < 8; j++)
            #pragma unroll
            for (int e = 0; e < 4; e++) acc[i][j][e] = 0.f;

    const int niter = K >> 5;

    stage_copy(A, Bt, K, crow, ccol, 0,  As,        Bs,        tid);
    cp_commit();
    stage_copy(A, Bt, K, crow, ccol, 32, As + GBUF, Bs + GBUF, tid);
    cp_commit();

    int buf = 0;
    for (int it = 0; it < niter; ++it) {
        cp_wait<1>();
        __syncthreads();

        const int nbuf = (buf + 2 >= 3) ? buf - 1 : buf + 2;
        if (it + 2 < niter)
            stage_copy(A, Bt, K, crow, ccol, (it + 2) << 5,
                       As + nbuf * GBUF, Bs + nbuf * GBUF, tid);
        cp_commit();

        const float* as = As + buf * GBUF;
        const float* bs = Bs + buf * GBUF;
        #pragma unroll
        for (int kk = 0; kk < 32; kk += 8) {
            uint32_t af[4][4], bf[8][2];
            #pragma unroll
            for (int mt = 0; mt < 4; mt++) {
                const int base = (rb + mt * 16 + g) * AST + kk + t;
                af[mt][0] = __float_as_uint(as[base]);
                af[mt][1] = __float_as_uint(as[base + 8 * AST]);
                af[mt][2] = __float_as_uint(as[base + 4]);
                af[mt][3] = __float_as_uint(as[base + 8 * AST + 4]);
            }
            #pragma unroll
            for (int nt = 0; nt < 8; nt++) {
                const int base = (cb + nt * 8 + g) * AST + kk + t;
                bf[nt][0] = __float_as_uint(bs[base]);
                bf[nt][1] = __float_as_uint(bs[base + 4]);
            }
            #pragma unroll
            for (int mt = 0; mt < 4; mt++)
                #pragma unroll
                for (int nt = 0; nt < 8; nt++)
                    mma_tf32_16x8x8(acc[mt][nt], af[mt], bf[nt]);
        }

        buf = (buf + 1 >= 3) ? 0 : buf + 1;
    }

    // -------- epilogue --------
    float* Cout = C;
    int colmask = ~0;
    bool dorope = false;
    if (EPI == 2) {
        const int sel = ccol >> 10;
        Cout = (sel == 0) ? C : (sel == 1 ? Ck : Cv);
        colmask = 1023;
        dorope = (sel < 2);
    }

    #pragma unroll
    for (int mt = 0; mt < 4; mt++) {
        #pragma unroll
        for (int half = 0; half < 2; half++) {
            const int r = crow + rb + mt * 16 + g + half * 8;
            const int s = r & (SS - 1);
            #pragma unroll
            for (int nt = 0; nt < 8; nt++) {
                const int cg = ccol + cb + nt * 8 + t * 2;
                float v0 = acc[mt][nt][half * 2 + 0] + bias[cg + 0];
                float v1 = acc[mt][nt][half * 2 + 1] + bias[cg + 1];
                if (EPI == 0 || EPI == 1) {
                    if (add) {
                        const float2 a2 = *(const float2*)(add + (size_t)r * N + cg);
                        v0 += a2.x; v1 += a2.y;
                    }
                    if (EPI == 1) {
                        const float t0 = tanh_fast(0.7978845608028654f * (v0 + 0.044715f * v0 * v0 * v0));
                        const float t1 = tanh_fast(0.7978845608028654f * (v1 + 0.044715f * v1 * v1 * v1));
                        v0 = 0.5f * v0 * (1.f + t0);
                        v1 = 0.5f * v1 * (1.f + t1);
                    }
                    *(float2*)(C + (size_t)r * N + cg) = make_float2(v0, v1);
                } else {
                    const int cl = cg & colmask;
                    if (dorope) {
                        const int i = (cl & 63) >> 1;
                        const float2 cs = g_ropetab[s * 32 + i];
                        const float n0 = v0 * cs.x - v1 * cs.y;
                        const float n1 = v1 * cs.x + v0 * cs.y;
                        v0 = n0; v1 = n1;
                    }
                    *(float2*)(Cout + (size_t)r * HD + cl) = make_float2(v0, v1);
                }
            }
        }
    }
}

// ============ merged prep: all transposes + rope table + bias pack =========
// blocks [0,4096): Wq/Wk/Wv/Wo 32x32 transpose tiles (1024 each)
// blocks [4096,8192): W1;  [8192,12288): W2
// blocks [12288,12544): rope table;  [12544,12556): bias pack
#define PREP_BLOCKS 12556
__global__ __launch_bounds__(256)
void prep_kernel(const float* __restrict__ Wq, const float* __restrict__ Wk,
                 const float* __restrict__ Wv, const float* __restrict__ Wo,
                 const float* __restrict__ W1, const float* __restrict__ W2,
                 const float* __restrict__ bq, const float* __restrict__ bk,
                 const float* __restrict__ bv)
{
    __shared__ float tbuf[32][33];
    const int bid = blockIdx.x;
    const int tid = threadIdx.x;

    if (bid < 12288) {
        const float* in;
        float* out;
        int R, C, tt;
        if (bid < 4096) {
            tt = bid & 1023;
            const int w = bid >> 10;
            in  = (w == 0) ? Wq : (w == 1) ? Wk : (w == 2) ? Wv : Wo;
            out = (w == 0) ? g_wqkvt : (w == 1) ? g_wqkvt + HD * HD
                : (w == 2) ? g_wqkvt + 2 * HD * HD : g_wot;
            R = HD; C = HD;
        } else if (bid < 8192) {
            tt = bid - 4096; in = W1; out = g_w1t; R = HD; C = FFD;
        } else {
            tt = bid - 8192; in = W2; out = g_w2t; R = FFD; C = HD;
        }
        const int nx = C >> 5;
        const int bx = (tt % nx) << 5;
        const int by = (tt / nx) << 5;
        const int tx = tid & 31, ty = tid >> 5;
        #pragma unroll
        for (int i = 0; i < 32; i += 8)
            tbuf[ty + i][tx] = in[(size_t)(by + ty + i) * C + bx + tx];
        __syncthreads();
        #pragma unroll
        for (int i = 0; i < 32; i += 8)
            out[(size_t)(bx + ty + i) * R + by + tx] = tf32r(tbuf[tx][ty + i]);
    } else if (bid < 12544) {
        const int idx = (bid - 12288) * 256 + tid;   // 0..65535 = 2048 x 32
        const int s = idx >> 5, i = idx & 31;
        const float inv = (float)pow(10000.0, -((double)(2 * i)) / 64.0);
        float sn, c;
        sincosf((float)s * inv, &sn, &c);
        g_ropetab[s * 32 + i] = make_float2(c, sn);
    } else {
        const int i = (bid - 12544) * 256 + tid;
        if (i < HD)           g_bqkv[i] = bq[i];
        else if (i < 2 * HD)  g_bqkv[i] = bk[i - HD];
        else if (i < 3 * HD)  g_bqkv[i] = bv[i - 2 * HD];
    }
}

// ============== Flash attention on tensor cores (tf32 mma.sync) ============
#define ATS 68
#define VST 72
#define KTILE (64 * ATS)
#define VTILE (64 * VST)

__device__ __forceinline__ void attn_copy_kv(const float* __restrict__ kbase,
                                             const float* __restrict__ vbase,
                                             int kt, float* ks, float* vs, int tid)
{
    #pragma unroll
    for (int l = 0; l < 4; l++) {
        const int idx = l * 256 + tid;
        const int r = idx >> 4, c4 = idx & 15;
        cp_async16(smem_u32(ks + r * ATS + c4 * 4), kbase + (size_t)(kt + r) * HD + c4 * 4);
        cp_async16(smem_u32(vs + r * VST + c4 * 4), vbase + (size_t)(kt + r) * HD + c4 * 4);
    }
}

__global__ __launch_bounds__(256, 2)
void attn_mma(const float* __restrict__ Q, const float* __restrict__ Kg,
              const float* __restrict__ Vg, float* __restrict__ O)
{
    extern __shared__ float sm[];
    float* Ks = sm;
    float* Vs = sm + 2 * KTILE;
    float* Ps = sm + 2 * KTILE + 2 * VTILE;

    const int tid  = threadIdx.x;
    const int wid  = tid >> 5;
    const int lane = tid & 31;
    const int g    = lane >> 2;
    const int t    = lane & 3;
    const int rb   = wid * 16;

    const int bh = blockIdx.y;
    const int b  = bh >> 4;
    const int h  = bh & 15;
    const int q0 = blockIdx.x * 128;

    const float qscale = 0.125f * LOG2E;

    const float* kbase = Kg + ((size_t)b * SS) * HD + h * DD;
    const float* vbase = Vg + ((size_t)b * SS) * HD + h * DD;

    attn_copy_kv(kbase, vbase, 0,  Ks,         Vs,         tid);
    cp_commit();
    attn_copy_kv(kbase, vbase, 64, Ks + KTILE, Vs + VTILE, tid);
    cp_commit();

    const float* qbase = Q + ((size_t)(b * SS + q0)) * HD + h * DD;
    #pragma unroll
    for (int l = 0; l < 8; l++) {
        const int idx = l * 256 + tid;
        const int r = idx >> 4, c4 = idx & 15;
        const float4 v4 = *(const float4*)(qbase + (size_t)r * HD + c4 * 4);
        float* d = Ps + r * ATS + c4 * 4;
        d[0] = tf32r(v4.x * qscale); d[1] = tf32r(v4.y * qscale);
        d[2] = tf32r(v4.z * qscale); d[3] = tf32r(v4.w * qscale);
    }
    __syncthreads();

    uint32_t qf[8][4];
    #pragma unroll
    for (int kk = 0; kk < 8; kk++) {
        const int base = (rb + g) * ATS + kk * 8 + t;
        qf[kk][0] = __float_as_uint(Ps[base]);
        qf[kk][1] = __float_as_uint(Ps[base + 8 * ATS]);
        qf[kk][2] = __float_as_uint(Ps[base + 4]);
        qf[kk][3] = __float_as_uint(Ps[base + 8 * ATS + 4]);
    }

    float acc[8][4];
    #pragma unroll
    for (int nt = 0; nt < 8; nt++)
        #pragma unroll
        for (int e = 0; e < 4; e++) acc[nt][e] = 0.f;
    float m0 = -1e30f, m1 = -1e30f, l0 = 0.f, l1 = 0.f;

    for (int it = 0; it < SS / 64; ++it) {
        cp_wait<1>();
        __syncthreads();
        const float* ks = Ks + (it & 1) * KTILE;
        const float* vs = Vs + (it & 1) * VTILE;

        float s[8][4];
        #pragma unroll
        for (int nt = 0; nt < 8; nt++)
            #pragma unroll
            for (int e = 0; e < 4; e++) s[nt][e] = 0.f;
        #pragma unroll
        for (int kk = 0; kk < 8; kk++) {
            uint32_t bf[8][2];
            #pragma unroll
            for (int nt = 0; nt < 8; nt++) {
                const int base = (nt * 8 + g) * ATS + kk * 8 + t;
                bf[nt][0] = __float_as_uint(ks[base]);
                bf[nt][1] = __float_as_uint(ks[base + 4]);
            }
            #pragma unroll
            for (int nt = 0; nt < 8; nt++)
                mma_tf32_16x8x8(s[nt], qf[kk], bf[nt]);
        }

        float rm0 = s[0][0], rm1 = s[0][2];
        #pragma unroll
        for (int nt = 0; nt < 8; nt++) {
            rm0 = fmaxf(rm0, fmaxf(s[nt][0], s[nt][1]));
            rm1 = fmaxf(rm1, fmaxf(s[nt][2], s[nt][3]));
        }
        rm0 = fmaxf(rm0, __shfl_xor_sync(0xffffffffu, rm0, 1));
        rm0 = fmaxf(rm0, __shfl_xor_sync(0xffffffffu, rm0, 2));
        rm1 = fmaxf(rm1, __shfl_xor_sync(0xffffffffu, rm1, 1));
        rm1 = fmaxf(rm1, __shfl_xor_sync(0xffffffffu, rm1, 2));
        const float mt0 = fmaxf(m0, rm0);
        const float mt1 = fmaxf(m1, rm1);
        if (mt0 > m0) {
            const float c0 = fexp2(m0 - mt0);
            l0 *= c0;
            #pragma unroll
            for (int nt = 0; nt < 8; nt++) { acc[nt][0] *= c0; acc[nt][1] *= c0; }
            m0 = mt0;
        }
        if (mt1 > m1) {
            const float c1 = fexp2(m1 - mt1);
            l1 *= c1;
            #pragma unroll
            for (int nt = 0; nt < 8; nt++) { acc[nt][2] *= c1; acc[nt][3] *= c1; }
            m1 = mt1;
        }

        float ps0 = 0.f, ps1 = 0.f;
        #pragma unroll
        for (int nt = 0; nt < 8; nt++) {
            const float p00 = tf32r(fexp2(s[nt][0] - m0));
            const float p01 = tf32r(fexp2(s[nt][1] - m0));
            const float p10 = tf32r(fexp2(s[nt][2] - m1));
            const float p11 = tf32r(fexp2(s[nt][3] - m1));
            ps0 += p00 + p01;
            ps1 += p10 + p11;
            *(float2*)&Ps[(rb + g) * ATS + nt * 8 + 2 * t]     = make_float2(p00, p01);
            *(float2*)&Ps[(rb + g + 8) * ATS + nt * 8 + 2 * t] = make_float2(p10, p11);
        }
        ps0 += __shfl_xor_sync(0xffffffffu, ps0, 1);
        ps0 += __shfl_xor_sync(0xffffffffu, ps0, 2);
        ps1 += __shfl_xor_sync(0xffffffffu, ps1, 1);
        ps1 += __shfl_xor_sync(0xffffffffu, ps1, 2);
        l0 += ps0;
        l1 += ps1;
        __syncwarp();

        #pragma unroll
        for (int kk = 0; kk < 8; kk++) {
            uint32_t af[4];
            const int base = (rb + g) * ATS + kk * 8 + t;
            af[0] = __float_as_uint(Ps[base]);
            af[1] = __float_as_uint(Ps[base + 8 * ATS]);
            af[2] = __float_as_uint(Ps[base + 4]);
            af[3] = __float_as_uint(Ps[base + 8 * ATS + 4]);
            const int vrow0 = (kk * 8 + t) * VST;
            const int vrow1 = (kk * 8 + t + 4) * VST;
            #pragma unroll
            for (int nt = 0; nt < 8; nt++) {
                uint32_t bf[2];
                bf[0] = __float_as_uint(vs[vrow0 + nt * 8 + g]);
                bf[1] = __float_as_uint(vs[vrow1 + nt * 8 + g]);
                mma_tf32_16x8x8(acc[nt], af, bf);
            }
        }

        __syncthreads();
        if (it + 2 < SS / 64)
            attn_copy_kv(kbase, vbase, (it + 2) * 64,
                         Ks + (it & 1) * KTILE, Vs + (it & 1) * VTILE, tid);
        cp_commit();
    }

    const float i0 = 1.f / l0;
    const float i1 = 1.f / l1;
    const int r0 = q0 + rb + g;
    const int r1 = r0 + 8;
    float* o0 = O + ((size_t)(b * SS + r0)) * HD + h * DD;
    float* o1 = O + ((size_t)(b * SS + r1)) * HD + h * DD;
    #pragma unroll
    for (int nt = 0; nt < 8; nt++) {
        *(float2*)(o0 + nt * 8 + 2 * t) = make_float2(acc[nt][0] * i0, acc[nt][1] * i0);
        *(float2*)(o1 + nt * 8 + 2 * t) = make_float2(acc[nt][2] * i1, acc[nt][3] * i1);
    }
}

// -------- LayerNorm over last dim (1024), eps=1e-12, single-pass -----------
__global__ __launch_bounds__(256)
void ln_kernel(const float* __restrict__ in, const float* __restrict__ gamma,
               const float* __restrict__ beta, float* __restrict__ out)
{
    const int row = blockIdx.x;
    const int tid = threadIdx.x;
    const float4 xv = ((const float4*)(in + (size_t)row * HD))[tid];

    __shared__ float2 red[8];
    float s  = xv.x + xv.y + xv.z + xv.w;
    float sq = xv.x*xv.x + xv.y*xv.y + xv.z*xv.z + xv.w*xv.w;
    #pragma unroll
    for (int o = 16; o > 0; o >>= 1) {
        s  += __shfl_xor_sync(0xffffffffu, s,  o);
        sq += __shfl_xor_sync(0xffffffffu, sq, o);
    }
    if ((tid & 31) == 0) red[tid >> 5] = make_float2(s, sq);
    __syncthreads();
    if (tid < 32) {
        float2 v = (tid < 8) ? red[tid] : make_float2(0.f, 0.f);
        float a = v.x, b2 = v.y;
        #pragma unroll
        for (int o = 4; o > 0; o >>= 1) {
            a  += __shfl_xor_sync(0xffffffffu, a,  o);
            b2 += __shfl_xor_sync(0xffffffffu, b2, o);
        }
        if (tid == 0) red[0] = make_float2(a, b2);
    }
    __syncthreads();
    const float mu   = red[0].x * (1.f / 1024.f);
    const float var  = red[0].y * (1.f / 1024.f) - mu * mu;
    const float rstd = rsqrtf(var + 1e-12f);

    const float4 gv = ((const float4*)gamma)[tid];
    const float4 bv = ((const float4*)beta )[tid];
    float4 ov;
    ov.x = (xv.x - mu) * rstd * gv.x + bv.x;
    ov.y = (xv.y - mu) * rstd * gv.y + bv.y;
    ov.z = (xv.z - mu) * rstd * gv.z + bv.z;
    ov.w = (xv.w - mu) * rstd * gv.w + bv.w;
    ((float4*)(out + (size_t)row * HD))[tid] = ov;
}

// ---------------- launch ----------------------------------------------------
extern "C" void kernel_launch(void* const* d_in, const int* in_sizes, int n_in,
                              void* d_out, int out_size)
{
    const float* x     = (const float*)d_in[0];
    const float* Wq    = (const float*)d_in[1];
    const float* bq    = (const float*)d_in[2];
    const float* Wk    = (const float*)d_in[3];
    const float* bk    = (const float*)d_in[4];
    const float* Wv    = (const float*)d_in[5];
    const float* bv    = (const float*)d_in[6];
    const float* Wo    = (const float*)d_in[7];
    const float* bo    = (const float*)d_in[8];
    const float* g1    = (const float*)d_in[9];
    const float* beta1 = (const float*)d_in[10];
    const float* W1    = (const float*)d_in[11];
    const float* b1    = (const float*)d_in[12];
    const float* W2    = (const float*)d_in[13];
    const float* b2    = (const float*)d_in[14];
    const float* g2    = (const float*)d_in[15];
    const float* beta2 = (const float*)d_in[16];
    float* out = (float*)d_out;

    float *q, *k, *v, *ctx, *r1, *h, *ff, *r2;
    float *wqkvt, *bqkv, *wot, *w1t, *w2t;
    cudaGetSymbolAddress((void**)&q,     g_q);
    cudaGetSymbolAddress((void**)&k,     g_k);
    cudaGetSymbolAddress((void**)&v,     g_v);
    cudaGetSymbolAddress((void**)&ctx,   g_ctx);
    cudaGetSymbolAddress((void**)&r1,    g_r1);
    cudaGetSymbolAddress((void**)&h,     g_h);
    cudaGetSymbolAddress((void**)&ff,    g_ff);
    cudaGetSymbolAddress((void**)&r2,    g_r2);
    cudaGetSymbolAddress((void**)&wqkvt, g_wqkvt);
    cudaGetSymbolAddress((void**)&bqkv,  g_bqkv);
    cudaGetSymbolAddress((void**)&wot,   g_wot);
    cudaGetSymbolAddress((void**)&w1t,   g_w1t);
    cudaGetSymbolAddress((void**)&w2t,   g_w2t);

    const int GEMM_SMEM = 6 * GBUF * 4;                             // 110592 B
    const int ATT_SMEM  = (2 * KTILE + 2 * VTILE + 128 * ATS) * 4;  // 106496 B
    cudaFuncSetAttribute(gemm_mma<0>, cudaFuncAttributeMaxDynamicSharedMemorySize, GEMM_SMEM);
    cudaFuncSetAttribute(gemm_mma<1>, cudaFuncAttributeMaxDynamicSharedMemorySize, GEMM_SMEM);
    cudaFuncSetAttribute(gemm_mma<2>, cudaFuncAttributeMaxDynamicSharedMemorySize, GEMM_SMEM);
    cudaFuncSetAttribute(attn_mma, cudaFuncAttributeMaxDynamicSharedMemorySize, ATT_SMEM);

    // one merged prep launch: transposes + rope table + bias pack
    prep_kernel<<<PREP_BLOCKS, 256>>>(Wq, Wk, Wv, Wo, W1, W2, bq, bk, bv);

    const dim3 gQKV(3 * HD / 128, BSR / 128);  // (24, 64)
    const dim3 gHd (HD  / 128,    BSR / 128);  // (8, 64)
    const dim3 gFf (FFD / 128,    BSR / 128);  // (32, 64)

    // fused QKV projection + bias + RoPE
    gemm_mma<2><<<gQKV, 128, GEMM_SMEM>>>(x, wqkvt, bqkv, nullptr, q, BSR, HD, HD, k, v);

    // Flash attention on tensor cores -> ctx
    attn_mma<<<dim3(SS / 128, BB * NHH), 256, ATT_SMEM>>>(q, k, v, ctx);

    // O projection + residual(x) -> r1 ; LN -> h
    gemm_mma<0><<<gHd, 128, GEMM_SMEM>>>(ctx, wot, bo, x, r1, BSR, HD, HD);
    ln_kernel<<<BSR, 256>>>(r1, g1, beta1, h);

    // FFN
    gemm_mma<1><<<gFf, 128, GEMM_SMEM>>>(h,  w1t, b1, nullptr, ff, BSR, FFD, HD);
    gemm_mma<0><<<gHd, 128, GEMM_SMEM>>>(ff, w2t, b2, h,       r2, BSR, HD, FFD);

    // final LN -> out
    ln_kernel<<<BSR, 256>>>(r2, g2, beta2, out);
}

// round 17
// speedup vs baseline: 1.3514x; 1.3514x over previous
#include <cuda_runtime.h>
#include <cuda_fp16.h>
#include <math.h>
#include <stdint.h>

// Problem constants
#define BB   4
#define SS   2048
#define HD   1024
#define NHH  16
#define DD   64
#define FFD  4096
#define BSR  (BB*SS)          // 8192 rows
#define LOG2E 1.4426950408889634f

// ---------------- scratch (device globals: no allocation allowed) ----------
__device__ float g_q  [BSR * HD];
__device__ float g_k  [BSR * HD];
__device__ float g_v  [BSR * HD];
__device__ float g_r1 [BSR * HD];
__device__ float g_h  [BSR * HD];
__device__ float g_r2 [BSR * HD];
// half activations (GEMM A operands)
__device__ __half g_xh  [BSR * HD];
__device__ __half g_ctxh[BSR * HD];
__device__ __half g_hh  [BSR * HD];
__device__ __half g_ffh [BSR * FFD];
// packed transposed (N,K) half weights
__device__ __half g_wqkvth[3 * HD * HD];
__device__ float  g_bqkv  [3 * HD];
__device__ __half g_woth[HD * HD];
__device__ __half g_w1th[FFD * HD];
__device__ __half g_w2th[HD * FFD];
// rope cos/sin table [S][32]
__device__ float2 g_ropetab[SS * 32];

__device__ __forceinline__ float tf32r(float x) {
    float r;
    asm("cvt.rna.tf32.f32 %0, %1;" : "=f"(r) : "f"(x));
    return r;
}
__device__ __forceinline__ float tanh_fast(float x) {
    float y;
    asm("tanh.approx.f32 %0, %1;" : "=f"(y) : "f"(x));
    return y;
}
__device__ __forceinline__ uint32_t smem_u32(const void* p) {
    uint32_t a;
    asm("{ .reg .u64 t; cvta.to.shared.u64 t, %1; cvt.u32.u64 %0, t; }" : "=r"(a) : "l"(p));
    return a;
}
__device__ __forceinline__ void cp_async16(uint32_t saddr, const void* g) {
    asm volatile("cp.async.cg.shared.global [%0], [%1], 16;" :: "r"(saddr), "l"(g));
}
__device__ __forceinline__ void cp_commit() {
    asm volatile("cp.async.commit_group;" ::: "memory");
}
template<int N> __device__ __forceinline__ void cp_wait() {
    asm volatile("cp.async.wait_group %0;" :: "n"(N) : "memory");
}

// fast exp2 on the fma/alu pipes (valid for x <= ~0; clamps at -126)
__device__ __forceinline__ float fexp2(float x) {
    x = fmaxf(x, -126.f);
    const float k = x + 12582912.f;
    const int   ik = __float_as_int(k) - 0x4B400000;
    const float f = x - (k - 12582912.f);
    float p = 9.6181291e-3f;
    p = fmaf(p, f, 5.5504109e-2f);
    p = fmaf(p, f, 2.4022651e-1f);
    p = fmaf(p, f, 6.9314718e-1f);
    p = fmaf(p, f, 1.0f);
    return __int_as_float(__float_as_int(p) + (ik << 23));
}

// tf32 m16n8k8 (attention only)
__device__ __forceinline__ void mma_tf32_16x8x8(float* c, const uint32_t* a, const uint32_t* b) {
    asm volatile(
        "mma.sync.aligned.m16n8k8.row.col.f32.tf32.tf32.f32 "
        "{%0,%1,%2,%3}, {%4,%5,%6,%7}, {%8,%9}, {%0,%1,%2,%3};"
        : "+f"(c[0]), "+f"(c[1]), "+f"(c[2]), "+f"(c[3])
        : "r"(a[0]), "r"(a[1]), "r"(a[2]), "r"(a[3]), "r"(b[0]), "r"(b[1]));
}
// fp16 m16n8k16 (GEMMs)
__device__ __forceinline__ void mma_f16_16x8x16(float* c, const uint32_t* a, const uint32_t* b) {
    asm volatile(
        "mma.sync.aligned.m16n8k16.row.col.f32.f16.f16.f32 "
        "{%0,%1,%2,%3}, {%4,%5,%6,%7}, {%8,%9}, {%0,%1,%2,%3};"
        : "+f"(c[0]), "+f"(c[1]), "+f"(c[2]), "+f"(c[3])
        : "r"(a[0]), "r"(a[1]), "r"(a[2]), "r"(a[3]), "r"(b[0]), "r"(b[1]));
}

// =================== fp16 mma.sync GEMM (3-stage cp.async) =================
// EPI: 0 = bias(+add) fp32 out, 1 = bias+gelu HALF out, 2 = fused QKV + RoPE
// BM=BN=128, BK=32 (halves), 256 threads (8 warps), warp tile 64x32.
#define HST 40                       // smem row stride in halves (32 + 8 pad)
#define HBUF (128 * HST)             // halves per operand per stage

__device__ __forceinline__ void stage_copy(const __half* __restrict__ A,
                                           const __half* __restrict__ Bt,
                                           int K, int crow, int ccol, int k0,
                                           __half* sa, __half* sb, int tid)
{
    #pragma unroll
    for (int i = 0; i < 2; i++) {
        const int chunk = i * 256 + tid;       // 512 chunks per operand
        const int row = chunk >> 2;            // 0..127
        const int c8  = (chunk & 3) * 8;       // halves
        cp_async16(smem_u32(sa + row * HST + c8), A  + (size_t)(crow + row) * K + k0 + c8);
        cp_async16(smem_u32(sb + row * HST + c8), Bt + (size_t)(ccol + row) * K + k0 + c8);
    }
}

template<int EPI>
__global__ __launch_bounds__(256, 2)
void gemm_mma(const __half* __restrict__ A, const __half* __restrict__ Bt,
              const float* __restrict__ bias, const float* __restrict__ add,
              float* __restrict__ C, int M, int N, int K,
              float* __restrict__ Ck = nullptr, float* __restrict__ Cv = nullptr)
{
    extern __shared__ __half hsm[];
    __half* As = hsm;                 // [3][HBUF]
    __half* Bs = hsm + 3 * HBUF;      // [3][HBUF]

    const int tid  = threadIdx.x;
    const int wid  = tid >> 5;
    const int lane = tid & 31;
    const int g    = lane >> 2;
    const int t    = lane & 3;

    const int crow = blockIdx.y * 128;
    const int ccol = blockIdx.x * 128;

    const int rb = (wid & 1) * 64;    // warp 64x32 tile
    const int cb = (wid >> 1) * 32;

    float acc[4][4][4];
    #pragma unroll
    for (int i = 0; i < 4; i++)
        #pragma unroll
        for (int j = 0; j < 4; j++)
            #pragma unroll
            for (int e = 0; e < 4; e++) acc[i][j][e] = 0.f;

    const int niter = K >> 5;

    stage_copy(A, Bt, K, crow, ccol, 0,  As,        Bs,        tid);
    cp_commit();
    stage_copy(A, Bt, K, crow, ccol, 32, As + HBUF, Bs + HBUF, tid);
    cp_commit();

    int buf = 0;
    for (int it = 0; it < niter; ++it) {
        cp_wait<1>();
        __syncthreads();

        const int nbuf = (buf + 2 >= 3) ? buf - 1 : buf + 2;
        if (it + 2 < niter)
            stage_copy(A, Bt, K, crow, ccol, (it + 2) << 5,
                       As + nbuf * HBUF, Bs + nbuf * HBUF, tid);
        cp_commit();

        const __half* as = As + buf * HBUF;
        const __half* bs = Bs + buf * HBUF;
        #pragma unroll
        for (int kk = 0; kk < 32; kk += 16) {
            uint32_t af[4][4], bf[4][2];
            #pragma unroll
            for (int mt = 0; mt < 4; mt++) {
                const int r0 = (rb + mt * 16 + g) * HST + kk + 2 * t;
                af[mt][0] = *(const uint32_t*)(as + r0);
                af[mt][1] = *(const uint32_t*)(as + r0 + 8 * HST);
                af[mt][2] = *(const uint32_t*)(as + r0 + 8);
                af[mt][3] = *(const uint32_t*)(as + r0 + 8 * HST + 8);
            }
            #pragma unroll
            for (int nt = 0; nt < 4; nt++) {
                const int r0 = (cb + nt * 8 + g) * HST + kk + 2 * t;
                bf[nt][0] = *(const uint32_t*)(bs + r0);
                bf[nt][1] = *(const uint32_t*)(bs + r0 + 8);
            }
            #pragma unroll
            for (int mt = 0; mt < 4; mt++)
                #pragma unroll
                for (int nt = 0; nt < 4; nt++)
                    mma_f16_16x8x16(acc[mt][nt], af[mt], bf[nt]);
        }

        buf = (buf + 1 >= 3) ? 0 : buf + 1;
    }

    // -------- epilogue --------
    float* Cout = C;
    int colmask = ~0;
    bool dorope = false;
    if (EPI == 2) {
        const int sel = ccol >> 10;
        Cout = (sel == 0) ? C : (sel == 1 ? Ck : Cv);
        colmask = 1023;
        dorope = (sel < 2);
    }

    #pragma unroll
    for (int mt = 0; mt < 4; mt++) {
        #pragma unroll
        for (int half_ = 0; half_ < 2; half_++) {
            const int r = crow + rb + mt * 16 + g + half_ * 8;
            const int s = r & (SS - 1);
            #pragma unroll
            for (int nt = 0; nt < 4; nt++) {
                const int cg = ccol + cb + nt * 8 + t * 2;
                float v0 = acc[mt][nt][half_ * 2 + 0] + bias[cg + 0];
                float v1 = acc[mt][nt][half_ * 2 + 1] + bias[cg + 1];
                if (EPI == 0) {
                    if (add) {
                        const float2 a2 = *(const float2*)(add + (size_t)r * N + cg);
                        v0 += a2.x; v1 += a2.y;
                    }
                    *(float2*)(C + (size_t)r * N + cg) = make_float2(v0, v1);
                } else if (EPI == 1) {
                    const float t0 = tanh_fast(0.7978845608028654f * (v0 + 0.044715f * v0 * v0 * v0));
                    const float t1 = tanh_fast(0.7978845608028654f * (v1 + 0.044715f * v1 * v1 * v1));
                    v0 = 0.5f * v0 * (1.f + t0);
                    v1 = 0.5f * v1 * (1.f + t1);
                    *(__half2*)((__half*)C + (size_t)r * N + cg) = __floats2half2_rn(v0, v1);
                } else {
                    const int cl = cg & colmask;
                    if (dorope) {
                        const int i = (cl & 63) >> 1;
                        const float2 cs = g_ropetab[s * 32 + i];
                        const float n0 = v0 * cs.x - v1 * cs.y;
                        const float n1 = v1 * cs.x + v0 * cs.y;
                        v0 = n0; v1 = n1;
                    }
                    *(float2*)(Cout + (size_t)r * HD + cl) = make_float2(v0, v1);
                }
            }
        }
    }
}

// ============ merged prep: transposes->half + x->half + rope + bias ========
// blocks [0,4096): Wq/Wk/Wv/Wo tiles; [4096,8192): W1; [8192,12288): W2
// [12288,16384): x -> half (2048 floats per block)
// [16384,16640): rope table;  [16640,16652): bias pack
#define PREP_BLOCKS 16652
__global__ __launch_bounds__(256)
void prep_kernel(const float* __restrict__ Wq, const float* __restrict__ Wk,
                 const float* __restrict__ Wv, const float* __restrict__ Wo,
                 const float* __restrict__ W1, const float* __restrict__ W2,
                 const float* __restrict__ x,
                 const float* __restrict__ bq, const float* __restrict__ bk,
                 const float* __restrict__ bv)
{
    __shared__ float tbuf[32][33];
    const int bid = blockIdx.x;
    const int tid = threadIdx.x;

    if (bid < 12288) {
        const float* in;
        __half* out;
        int R, C, tt;
        if (bid < 4096) {
            tt = bid & 1023;
            const int w = bid >> 10;
            in  = (w == 0) ? Wq : (w == 1) ? Wk : (w == 2) ? Wv : Wo;
            out = (w == 0) ? g_wqkvth : (w == 1) ? g_wqkvth + HD * HD
                : (w == 2) ? g_wqkvth + 2 * HD * HD : g_woth;
            R = HD; C = HD;
        } else if (bid < 8192) {
            tt = bid - 4096; in = W1; out = g_w1th; R = HD; C = FFD;
        } else {
            tt = bid - 8192; in = W2; out = g_w2th; R = FFD; C = HD;
        }
        const int nx = C >> 5;
        const int bx = (tt % nx) << 5;
        const int by = (tt / nx) << 5;
        const int tx = tid & 31, ty = tid >> 5;
        #pragma unroll
        for (int i = 0; i < 32; i += 8)
            tbuf[ty + i][tx] = in[(size_t)(by + ty + i) * C + bx + tx];
        __syncthreads();
        #pragma unroll
        for (int i = 0; i < 32; i += 8)
            out[(size_t)(bx + ty + i) * R + by + tx] = __float2half_rn(tbuf[tx][ty + i]);
    } else if (bid < 16384) {
        const size_t base = (size_t)(bid - 12288) * 2048 + tid * 8;
        const float4 v0 = *(const float4*)(x + base);
        const float4 v1 = *(const float4*)(x + base + 4);
        __half2* dst = (__half2*)(g_xh + base);
        dst[0] = __floats2half2_rn(v0.x, v0.y);
        dst[1] = __floats2half2_rn(v0.z, v0.w);
        dst[2] = __floats2half2_rn(v1.x, v1.y);
        dst[3] = __floats2half2_rn(v1.z, v1.w);
    } else if (bid < 16640) {
        const int idx = (bid - 16384) * 256 + tid;   // 2048 x 32
        const int s = idx >> 5, i = idx & 31;
        const float inv = (float)pow(10000.0, -((double)(2 * i)) / 64.0);
        float sn, c;
        sincosf((float)s * inv, &sn, &c);
        g_ropetab[s * 32 + i] = make_float2(c, sn);
    } else {
        const int i = (bid - 16640) * 256 + tid;
        if (i < HD)           g_bqkv[i] = bq[i];
        else if (i < 2 * HD)  g_bqkv[i] = bk[i - HD];
        else if (i < 3 * HD)  g_bqkv[i] = bv[i - 2 * HD];
    }
}

// ============== Flash attention on tensor cores (tf32 mma.sync) ============
// unchanged compute; epilogue writes HALF ctx (O-proj A operand).
#define ATS 68
#define VST 72
#define KTILE (64 * ATS)
#define VTILE (64 * VST)

__device__ __forceinline__ void attn_copy_kv(const float* __restrict__ kbase,
                                             const float* __restrict__ vbase,
                                             int kt, float* ks, float* vs, int tid)
{
    #pragma unroll
    for (int l = 0; l < 4; l++) {
        const int idx = l * 256 + tid;
        const int r = idx >> 4, c4 = idx & 15;
        cp_async16(smem_u32(ks + r * ATS + c4 * 4), kbase + (size_t)(kt + r) * HD + c4 * 4);
        cp_async16(smem_u32(vs + r * VST + c4 * 4), vbase + (size_t)(kt + r) * HD + c4 * 4);
    }
}

__global__ __launch_bounds__(256, 2)
void attn_mma(const float* __restrict__ Q, const float* __restrict__ Kg,
              const float* __restrict__ Vg, __half* __restrict__ Oh)
{
    extern __shared__ float sm[];
    float* Ks = sm;
    float* Vs = sm + 2 * KTILE;
    float* Ps = sm + 2 * KTILE + 2 * VTILE;

    const int tid  = threadIdx.x;
    const int wid  = tid >> 5;
    const int lane = tid & 31;
    const int g    = lane >> 2;
    const int t    = lane & 3;
    const int rb   = wid * 16;

    const int bh = blockIdx.y;
    const int b  = bh >> 4;
    const int h  = bh & 15;
    const int q0 = blockIdx.x * 128;

    const float qscale = 0.125f * LOG2E;

    const float* kbase = Kg + ((size_t)b * SS) * HD + h * DD;
    const float* vbase = Vg + ((size_t)b * SS) * HD + h * DD;

    attn_copy_kv(kbase, vbase, 0,  Ks,         Vs,         tid);
    cp_commit();
    attn_copy_kv(kbase, vbase, 64, Ks + KTILE, Vs + VTILE, tid);
    cp_commit();

    const float* qbase = Q + ((size_t)(b * SS + q0)) * HD + h * DD;
    #pragma unroll
    for (int l = 0; l < 8; l++) {
        const int idx = l * 256 + tid;
        const int r = idx >> 4, c4 = idx & 15;
        const float4 v4 = *(const float4*)(qbase + (size_t)r * HD + c4 * 4);
        float* d = Ps + r * ATS + c4 * 4;
        d[0] = tf32r(v4.x * qscale); d[1] = tf32r(v4.y * qscale);
        d[2] = tf32r(v4.z * qscale); d[3] = tf32r(v4.w * qscale);
    }
    __syncthreads();

    uint32_t qf[8][4];
    #pragma unroll
    for (int kk = 0; kk < 8; kk++) {
        const int base = (rb + g) * ATS + kk * 8 + t;
        qf[kk][0] = __float_as_uint(Ps[base]);
        qf[kk][1] = __float_as_uint(Ps[base + 8 * ATS]);
        qf[kk][2] = __float_as_uint(Ps[base + 4]);
        qf[kk][3] = __float_as_uint(Ps[base + 8 * ATS + 4]);
    }

    float acc[8][4];
    #pragma unroll
    for (int nt = 0; nt < 8; nt++)
        #pragma unroll
        for (int e = 0; e < 4; e++) acc[nt][e] = 0.f;
    float m0 = -1e30f, m1 = -1e30f, l0 = 0.f, l1 = 0.f;

    for (int it = 0; it < SS / 64; ++it) {
        cp_wait<1>();
        __syncthreads();
        const float* ks = Ks + (it & 1) * KTILE;
        const float* vs = Vs + (it & 1) * VTILE;

        float s[8][4];
        #pragma unroll
        for (int nt = 0; nt < 8; nt++)
            #pragma unroll
            for (int e = 0; e < 4; e++) s[nt][e] = 0.f;
        #pragma unroll
        for (int kk = 0; kk < 8; kk++) {
            uint32_t bf[8][2];
            #pragma unroll
            for (int nt = 0; nt < 8; nt++) {
                const int base = (nt * 8 + g) * ATS + kk * 8 + t;
                bf[nt][0] = __float_as_uint(ks[base]);
                bf[nt][1] = __float_as_uint(ks[base + 4]);
            }
            #pragma unroll
            for (int nt = 0; nt < 8; nt++)
                mma_tf32_16x8x8(s[nt], qf[kk], bf[nt]);
        }

        float rm0 = s[0][0], rm1 = s[0][2];
        #pragma unroll
        for (int nt = 0; nt < 8; nt++) {
            rm0 = fmaxf(rm0, fmaxf(s[nt][0], s[nt][1]));
            rm1 = fmaxf(rm1, fmaxf(s[nt][2], s[nt][3]));
        }
        rm0 = fmaxf(rm0, __shfl_xor_sync(0xffffffffu, rm0, 1));
        rm0 = fmaxf(rm0, __shfl_xor_sync(0xffffffffu, rm0, 2));
        rm1 = fmaxf(rm1, __shfl_xor_sync(0xffffffffu, rm1, 1));
        rm1 = fmaxf(rm1, __shfl_xor_sync(0xffffffffu, rm1, 2));
        const float mt0 = fmaxf(m0, rm0);
        const float mt1 = fmaxf(m1, rm1);
        if (mt0 > m0) {
            const float c0 = fexp2(m0 - mt0);
            l0 *= c0;
            #pragma unroll
            for (int nt = 0; nt < 8; nt++) { acc[nt][0] *= c0; acc[nt][1] *= c0; }
            m0 = mt0;
        }
        if (mt1 > m1) {
            const float c1 = fexp2(m1 - mt1);
            l1 *= c1;
            #pragma unroll
            for (int nt = 0; nt < 8; nt++) { acc[nt][2] *= c1; acc[nt][3] *= c1; }
            m1 = mt1;
        }

        float ps0 = 0.f, ps1 = 0.f;
        #pragma unroll
        for (int nt = 0; nt < 8; nt++) {
            const float p00 = tf32r(fexp2(s[nt][0] - m0));
            const float p01 = tf32r(fexp2(s[nt][1] - m0));
            const float p10 = tf32r(fexp2(s[nt][2] - m1));
            const float p11 = tf32r(fexp2(s[nt][3] - m1));
            ps0 += p00 + p01;
            ps1 += p10 + p11;
            *(float2*)&Ps[(rb + g) * ATS + nt * 8 + 2 * t]     = make_float2(p00, p01);
            *(float2*)&Ps[(rb + g + 8) * ATS + nt * 8 + 2 * t] = make_float2(p10, p11);
        }
        ps0 += __shfl_xor_sync(0xffffffffu, ps0, 1);
        ps0 += __shfl_xor_sync(0xffffffffu, ps0, 2);
        ps1 += __shfl_xor_sync(0xffffffffu, ps1, 1);
        ps1 += __shfl_xor_sync(0xffffffffu, ps1, 2);
        l0 += ps0;
        l1 += ps1;
        __syncwarp();

        #pragma unroll
        for (int kk = 0; kk < 8; kk++) {
            uint32_t af[4];
            const int base = (rb + g) * ATS + kk * 8 + t;
            af[0] = __float_as_uint(Ps[base]);
            af[1] = __float_as_uint(Ps[base + 8 * ATS]);
            af[2] = __float_as_uint(Ps[base + 4]);
            af[3] = __float_as_uint(Ps[base + 8 * ATS + 4]);
            const int vrow0 = (kk * 8 + t) * VST;
            const int vrow1 = (kk * 8 + t + 4) * VST;
            #pragma unroll
            for (int nt = 0; nt < 8; nt++) {
                uint32_t bf[2];
                bf[0] = __float_as_uint(vs[vrow0 + nt * 8 + g]);
                bf[1] = __float_as_uint(vs[vrow1 + nt * 8 + g]);
                mma_tf32_16x8x8(acc[nt], af, bf);
            }
        }

        __syncthreads();
        if (it + 2 < SS / 64)
            attn_copy_kv(kbase, vbase, (it + 2) * 64,
                         Ks + (it & 1) * KTILE, Vs + (it & 1) * VTILE, tid);
        cp_commit();
    }

    const float i0 = 1.f / l0;
    const float i1 = 1.f / l1;
    const int r0 = q0 + rb + g;
    const int r1 = r0 + 8;
    __half* o0 = Oh + ((size_t)(b * SS + r0)) * HD + h * DD;
    __half* o1 = Oh + ((size_t)(b * SS + r1)) * HD + h * DD;
    #pragma unroll
    for (int nt = 0; nt < 8; nt++) {
        *(__half2*)(o0 + nt * 8 + 2 * t) = __floats2half2_rn(acc[nt][0] * i0, acc[nt][1] * i0);
        *(__half2*)(o1 + nt * 8 + 2 * t) = __floats2half2_rn(acc[nt][2] * i1, acc[nt][3] * i1);
    }
}

// -------- LayerNorm (1024), eps=1e-12, single-pass, optional half copy -----
__global__ __launch_bounds__(256)
void ln_kernel(const float* __restrict__ in, const float* __restrict__ gamma,
               const float* __restrict__ beta, float* __restrict__ out,
               __half* __restrict__ outh)
{
    const int row = blockIdx.x;
    const int tid = threadIdx.x;
    const float4 xv = ((const float4*)(in + (size_t)row * HD))[tid];

    __shared__ float2 red[8];
    float s  = xv.x + xv.y + xv.z + xv.w;
    float sq = xv.x*xv.x + xv.y*xv.y + xv.z*xv.z + xv.w*xv.w;
    #pragma unroll
    for (int o = 16; o > 0; o >>= 1) {
        s  += __shfl_xor_sync(0xffffffffu, s,  o);
        sq += __shfl_xor_sync(0xffffffffu, sq, o);
    }
    if ((tid & 31) == 0) red[tid >> 5] = make_float2(s, sq);
    __syncthreads();
    if (tid < 32) {
        float2 v = (tid < 8) ? red[tid] : make_float2(0.f, 0.f);
        float a = v.x, b2 = v.y;
        #pragma unroll
        for (int o = 4; o > 0; o >>= 1) {
            a  += __shfl_xor_sync(0xffffffffu, a,  o);
            b2 += __shfl_xor_sync(0xffffffffu, b2, o);
        }
        if (tid == 0) red[0] = make_float2(a, b2);
    }
    __syncthreads();
    const float mu   = red[0].x * (1.f / 1024.f);
    const float var  = red[0].y * (1.f / 1024.f) - mu * mu;
    const float rstd = rsqrtf(var + 1e-12f);

    const float4 gv = ((const float4*)gamma)[tid];
    const float4 bv = ((const float4*)beta )[tid];
    float4 ov;
    ov.x = (xv.x - mu) * rstd * gv.x + bv.x;
    ov.y = (xv.y - mu) * rstd * gv.y + bv.y;
    ov.z = (xv.z - mu) * rstd * gv.z + bv.z;
    ov.w = (xv.w - mu) * rstd * gv.w + bv.w;
    ((float4*)(out + (size_t)row * HD))[tid] = ov;
    if (outh) {
        __half2* dh = (__half2*)(outh + (size_t)row * HD) + tid * 2;
        dh[0] = __floats2half2_rn(ov.x, ov.y);
        dh[1] = __floats2half2_rn(ov.z, ov.w);
    }
}

// ---------------- launch ----------------------------------------------------
extern "C" void kernel_launch(void* const* d_in, const int* in_sizes, int n_in,
                              void* d_out, int out_size)
{
    const float* x     = (const float*)d_in[0];
    const float* Wq    = (const float*)d_in[1];
    const float* bq    = (const float*)d_in[2];
    const float* Wk    = (const float*)d_in[3];
    const float* bk    = (const float*)d_in[4];
    const float* Wv    = (const float*)d_in[5];
    const float* bv    = (const float*)d_in[6];
    const float* Wo    = (const float*)d_in[7];
    const float* bo    = (const float*)d_in[8];
    const float* g1    = (const float*)d_in[9];
    const float* beta1 = (const float*)d_in[10];
    const float* W1    = (const float*)d_in[11];
    const float* b1    = (const float*)d_in[12];
    const float* W2    = (const float*)d_in[13];
    const float* b2    = (const float*)d_in[14];
    const float* g2    = (const float*)d_in[15];
    const float* beta2 = (const float*)d_in[16];
    float* out = (float*)d_out;

    float *q, *k, *v, *r1, *h, *r2, *bqkv;
    __half *xh, *ctxh, *hh, *ffh, *wqkvth, *woth, *w1th, *w2th;
    cudaGetSymbolAddress((void**)&q,      g_q);
    cudaGetSymbolAddress((void**)&k,      g_k);
    cudaGetSymbolAddress((void**)&v,      g_v);
    cudaGetSymbolAddress((void**)&r1,     g_r1);
    cudaGetSymbolAddress((void**)&h,      g_h);
    cudaGetSymbolAddress((void**)&r2,     g_r2);
    cudaGetSymbolAddress((void**)&xh,     g_xh);
    cudaGetSymbolAddress((void**)&ctxh,   g_ctxh);
    cudaGetSymbolAddress((void**)&hh,     g_hh);
    cudaGetSymbolAddress((void**)&ffh,    g_ffh);
    cudaGetSymbolAddress((void**)&wqkvth, g_wqkvth);
    cudaGetSymbolAddress((void**)&bqkv,   g_bqkv);
    cudaGetSymbolAddress((void**)&woth,   g_woth);
    cudaGetSymbolAddress((void**)&w1th,   g_w1th);
    cudaGetSymbolAddress((void**)&w2th,   g_w2th);

    const int GEMM_SMEM = 6 * HBUF * 2;                             // 61440 B
    const int ATT_SMEM  = (2 * KTILE + 2 * VTILE + 128 * ATS) * 4;  // 106496 B
    cudaFuncSetAttribute(gemm_mma<0>, cudaFuncAttributeMaxDynamicSharedMemorySize, GEMM_SMEM);
    cudaFuncSetAttribute(gemm_mma<1>, cudaFuncAttributeMaxDynamicSharedMemorySize, GEMM_SMEM);
    cudaFuncSetAttribute(gemm_mma<2>, cudaFuncAttributeMaxDynamicSharedMemorySize, GEMM_SMEM);
    cudaFuncSetAttribute(attn_mma, cudaFuncAttributeMaxDynamicSharedMemorySize, ATT_SMEM);

    // one merged prep launch: weight transposes->half, x->half, rope, bias
    prep_kernel<<<PREP_BLOCKS, 256>>>(Wq, Wk, Wv, Wo, W1, W2, x, bq, bk, bv);

    const dim3 gQKV(3 * HD / 128, BSR / 128);  // (24, 64)
    const dim3 gHd (HD  / 128,    BSR / 128);  // (8, 64)
    const dim3 gFf (FFD / 128,    BSR / 128);  // (32, 64)

    // fused QKV projection + bias + RoPE (fp16 inputs, fp32 out)
    gemm_mma<2><<<gQKV, 256, GEMM_SMEM>>>(xh, wqkvth, bqkv, nullptr, q, BSR, HD, HD, k, v);

    // Flash attention (tf32) -> half ctx
    attn_mma<<<dim3(SS / 128, BB * NHH), 256, ATT_SMEM>>>(q, k, v, ctxh);

    // O projection + residual(x) -> r1 ; LN -> h (+half copy)
    gemm_mma<0><<<gHd, 256, GEMM_SMEM>>>(ctxh, woth, bo, x, r1, BSR, HD, HD);
    ln_kernel<<<BSR, 256>>>(r1, g1, beta1, h, hh);

    // FFN: W1 + gelu -> half ff ; W2 + residual(h) -> r2
    gemm_mma<1><<<gFf, 256, GEMM_SMEM>>>(hh, w1th, b1, nullptr, (float*)ffh, BSR, FFD, HD);
    gemm_mma<0><<<gHd, 256, GEMM_SMEM>>>(ffh, w2th, b2, h, r2, BSR, HD, FFD);

    // final LN -> out
    ln_kernel<<<BSR, 256>>>(r2, g2, beta2, out, nullptr);
}